// round 1
// baseline (speedup 1.0000x reference)
#include <cuda_runtime.h>

#define BB 32
#define CC 128
#define HH 56
#define WW 56
#define SIZE (CC*HH*WW)          // 401408
#define HW   (HH*WW)             // 3136
#define EPSV 1e-5f
#define SLOPE 0.1f

// scratch: z = leakyrelu(bn1(cfc combine)) in [B, C, H, W] layout
__device__ float g_z[BB*SIZE];   // 51.4 MB static scratch (allocation-free rule)

// ---------------------------------------------------------------------------
// Kernel 1: elementwise combine + BN1d + LeakyReLU.
// Grid over SIZE; each thread folds BN into (ws0, ws1, shift) once and loops
// over the 32 batches (param arrays read exactly once from DRAM).
// ---------------------------------------------------------------------------
__global__ void scrm_fuse1(const float* __restrict__ ax,
                           const float* __restrict__ mx,
                           const float* __restrict__ cfc,
                           const float* __restrict__ gamma,
                           const float* __restrict__ beta,
                           const float* __restrict__ mean,
                           const float* __restrict__ var) {
    int i = blockIdx.x * blockDim.x + threadIdx.x;
    if (i >= SIZE) return;
    float w0 = cfc[2 * i];
    float w1 = cfc[2 * i + 1];
    float s  = gamma[i] * rsqrtf(var[i] + EPSV);
    float sh = beta[i] - mean[i] * s;
    float ws0 = w0 * s;
    float ws1 = w1 * s;
#pragma unroll 4
    for (int b = 0; b < BB; b++) {
        int idx = b * SIZE + i;
        float z = fmaf(ws0, ax[idx], fmaf(ws1, mx[idx], sh));
        g_z[idx] = (z > 0.f) ? z : SLOPE * z;
    }
}

// ---------------------------------------------------------------------------
// Kernel 2: 3x3 conv (stride 1, pad 1) + bias + BN2d + LeakyReLU.
// Block tile: all 128 output channels x (2 rows x 56 cols) for one batch.
// Thread tile: 8 oc x 7 px. K-loop over input channels in chunks of 8.
//   smem input : [8 ic][4 rows][58 cols]  (halo + zero padding)   7.4 KB
//   smem weight: [72 (ic*9+k)][stride 129][oc]                    37.2 KB
// Thread map: tid = pg*16 + og  -> warp = 2 pixel-groups x 16 oc-groups:
//   input LDS = 2 broadcast addresses/warp, weight LDS = lane-consecutive.
// ---------------------------------------------------------------------------
#define ICC 8
#define WS_STRIDE 129

__global__ void __launch_bounds__(256, 2)
scrm_conv3x3(const float* __restrict__ gw,   // [128][128][3][3]
             const float* __restrict__ gb,   // [128] bias
             const float* __restrict__ g2,   // bn2_gamma
             const float* __restrict__ b2,   // bn2_beta
             const float* __restrict__ m2,   // bn2_mean
             const float* __restrict__ v2,   // bn2_var
             float* __restrict__ out) {
    __shared__ float in_s[ICC][4][58];
    __shared__ float w_s[72 * WS_STRIDE];

    const int b     = blockIdx.y;
    const int y0    = blockIdx.x * 2;        // 28 row-blocks * 2 rows = 56
    const int tid   = threadIdx.x;
    const int og    = tid & 15;              // oc group: oc = og + 16*j
    const int pg    = tid >> 4;              // pixel group 0..15
    const int pgrow = pg >> 3;               // 0..1
    const int pgcol = pg & 7;                // 0..7  -> 7 cols each
    const int xbase = pgcol * 7;
    const int yout  = y0 + pgrow;

    float acc[8][7];
#pragma unroll
    for (int j = 0; j < 8; j++)
#pragma unroll
        for (int i = 0; i < 7; i++) acc[j][i] = 0.f;

    const float* zb = g_z + b * SIZE;

    for (int cc = 0; cc < CC / ICC; cc++) {
        const int ic0 = cc * ICC;

        // --- load input tile (with halo, zero-padded) ---
        for (int i = tid; i < ICC * 4 * 58; i += 256) {
            int ic   = i / 232;
            int rem  = i % 232;
            int r    = rem / 58;
            int ccol = rem % 58;
            int y = y0 - 1 + r;
            int x = ccol - 1;
            float v = 0.f;
            if ((unsigned)y < 56u && (unsigned)x < 56u)
                v = zb[(ic0 + ic) * HW + y * WW + x];
            in_s[ic][r][ccol] = v;
        }
        // --- load weight chunk, transposed to [ic*9+k][oc] (padded stride) ---
        for (int i = tid; i < CC * ICC * 9; i += 256) {
            int oc  = i / 72;
            int rem = i % 72;                 // = ic*9 + kh*3 + kw
            w_s[rem * WS_STRIDE + oc] = gw[oc * 1152 + ic0 * 9 + rem];
        }
        __syncthreads();

        // --- compute ---
#pragma unroll 2
        for (int ic = 0; ic < ICC; ic++) {
#pragma unroll
            for (int kh = 0; kh < 3; kh++) {
                const float* inrow = &in_s[ic][pgrow + kh][xbase];
                float x9[9];
#pragma unroll
                for (int i = 0; i < 9; i++) x9[i] = inrow[i];
#pragma unroll
                for (int kw = 0; kw < 3; kw++) {
                    const float* wrow = &w_s[(ic * 9 + kh * 3 + kw) * WS_STRIDE + og];
#pragma unroll
                    for (int j = 0; j < 8; j++) {
                        float wv = wrow[16 * j];
#pragma unroll
                        for (int i = 0; i < 7; i++)
                            acc[j][i] = fmaf(wv, x9[kw + i], acc[j][i]);
                    }
                }
            }
        }
        __syncthreads();
    }

    // --- epilogue: bias + BN2d + LeakyReLU ---
#pragma unroll
    for (int j = 0; j < 8; j++) {
        int oc  = og + 16 * j;
        float s  = g2[oc] * rsqrtf(v2[oc] + EPSV);
        float sh = fmaf(gb[oc] - m2[oc], s, b2[oc]);
        float* op = out + ((b * CC + oc) * HH + yout) * WW + xbase;
#pragma unroll
        for (int i = 0; i < 7; i++) {
            float v = fmaf(acc[j][i], s, sh);
            op[i] = (v > 0.f) ? v : SLOPE * v;
        }
    }
}

// ---------------------------------------------------------------------------
// launch
// ---------------------------------------------------------------------------
extern "C" void kernel_launch(void* const* d_in, const int* in_sizes, int n_in,
                              void* d_out, int out_size) {
    const float* ax   = (const float*)d_in[0];
    const float* mx   = (const float*)d_in[1];
    const float* cfc  = (const float*)d_in[2];
    const float* bng  = (const float*)d_in[3];
    const float* bnb  = (const float*)d_in[4];
    const float* bnm  = (const float*)d_in[5];
    const float* bnv  = (const float*)d_in[6];
    const float* cw   = (const float*)d_in[7];
    const float* cb   = (const float*)d_in[8];
    const float* g2   = (const float*)d_in[9];
    const float* b2   = (const float*)d_in[10];
    const float* m2   = (const float*)d_in[11];
    const float* v2   = (const float*)d_in[12];
    float* out = (float*)d_out;

    scrm_fuse1<<<(SIZE + 255) / 256, 256>>>(ax, mx, cfc, bng, bnb, bnm, bnv);

    dim3 grid(HH / 2, BB);   // 28 row-blocks x 32 batches
    scrm_conv3x3<<<grid, 256>>>(cw, cb, g2, b2, m2, v2, out);
}

// round 3
// speedup vs baseline: 3.1357x; 3.1357x over previous
#include <cuda_runtime.h>
#include <cstdint>

#define BB 32
#define CC 128
#define HH 56
#define WW 56
#define SIZE (CC*HH*WW)          // 401408
#define HW   (HH*WW)             // 3136
#define EPSV 1e-5f
#define SLOPE 0.1f
#define SK 136                    // smem row stride (floats), ≡ 8 mod 32

// scratch (allocation-free rule: __device__ globals)
__device__ float g_z[BB*SIZE];        // 51.4 MB: z = leakyrelu(bn1(combine))
__device__ float g_wt[9*CC*CC];       // [tap][ic][oc], tf32-rounded weights
__device__ float g_s2[CC];            // fused epilogue scale
__device__ float g_sh2[CC];           // fused epilogue shift (incl. conv bias)

__device__ __forceinline__ uint32_t f2tf32(float v) {
    uint32_t r; asm("cvt.rna.tf32.f32 %0, %1;" : "=r"(r) : "f"(v)); return r;
}

__device__ __forceinline__ void mma_tf32(float* d, const uint32_t* a,
                                         const uint32_t* b) {
    asm volatile(
        "mma.sync.aligned.m16n8k8.row.col.f32.tf32.tf32.f32 "
        "{%0,%1,%2,%3}, {%4,%5,%6,%7}, {%8,%9}, {%0,%1,%2,%3};"
        : "+f"(d[0]), "+f"(d[1]), "+f"(d[2]), "+f"(d[3])
        : "r"(a[0]), "r"(a[1]), "r"(a[2]), "r"(a[3]),
          "r"(b[0]), "r"(b[1]));
}

// ---------------------------------------------------------------------------
// Kernel 1: elementwise combine + BN1d + LeakyReLU
// ---------------------------------------------------------------------------
__global__ void scrm_fuse1(const float* __restrict__ ax,
                           const float* __restrict__ mx,
                           const float* __restrict__ cfc,
                           const float* __restrict__ gamma,
                           const float* __restrict__ beta,
                           const float* __restrict__ mean,
                           const float* __restrict__ var) {
    int i = blockIdx.x * blockDim.x + threadIdx.x;
    if (i >= SIZE) return;
    float w0 = cfc[2 * i];
    float w1 = cfc[2 * i + 1];
    float s  = gamma[i] * rsqrtf(var[i] + EPSV);
    float sh = beta[i] - mean[i] * s;
    float ws0 = w0 * s;
    float ws1 = w1 * s;
#pragma unroll 4
    for (int b = 0; b < BB; b++) {
        int idx = b * SIZE + i;
        float z = fmaf(ws0, ax[idx], fmaf(ws1, mx[idx], sh));
        g_z[idx] = (z > 0.f) ? z : SLOPE * z;
    }
}

// ---------------------------------------------------------------------------
// Kernel 1b: weight transpose [oc][ic][3][3] -> [tap][ic][oc], tf32-rounded
// ---------------------------------------------------------------------------
__global__ void scrm_wtrans(const float* __restrict__ gw) {
    int i = blockIdx.x * 256 + threadIdx.x;      // over 9*128*128
    if (i >= 9 * CC * CC) return;
    int oc = i & 127;
    int ic = (i >> 7) & 127;
    int t  = i >> 14;
    float v = gw[oc * 1152 + ic * 9 + t];
    g_wt[i] = __uint_as_float(f2tf32(v));        // [t][ic][oc]
}

// ---------------------------------------------------------------------------
// Kernel 1c: fold conv bias + BN2d into per-oc scale/shift
// ---------------------------------------------------------------------------
__global__ void scrm_epiparams(const float* __restrict__ cb,
                               const float* __restrict__ g2,
                               const float* __restrict__ b2,
                               const float* __restrict__ m2,
                               const float* __restrict__ v2) {
    int oc = threadIdx.x;
    float s = g2[oc] * rsqrtf(v2[oc] + EPSV);
    g_s2[oc]  = s;
    g_sh2[oc] = fmaf(cb[oc] - m2[oc], s, b2[oc]);
}

// ---------------------------------------------------------------------------
// Kernel 2: tf32 mma.sync implicit-GEMM 3x3 conv + fused epilogue.
// CTA: 256 thr (8 warps, 2 M x 4 N). Block tile 128 px x 128 oc, K-chunk 32.
// Warp tile 64x32 (4 m-frags x 4 n-frags of m16n8k8). Acc in registers.
// Smem k-major, stride 136 -> STS and all fragment LDS conflict-free.
// ---------------------------------------------------------------------------
__global__ void __launch_bounds__(256, 2)
scrm_conv_mma(float* __restrict__ out) {
    __shared__ float As[32 * SK];   // [k][px]
    __shared__ float Bs[32 * SK];   // [k][oc]

    const int tid  = threadIdx.x;
    const int wid  = tid >> 5;
    const int lane = tid & 31;
    const int warp_m = wid >> 2;    // 0..1
    const int warp_n = wid & 3;     // 0..3
    const int g   = lane >> 2;      // groupID 0..7
    const int tig = lane & 3;       // 0..3

    // gather role: this thread owns pixel px, k rows {krow, krow+2, ...}
    const int px   = tid & 127;
    const int krow = tid >> 7;      // 0 or 1
    const int gp   = blockIdx.x * 128 + px;
    const int bb   = gp / HW;
    const int pp   = gp % HW;
    const int yy   = pp / WW, xx = pp % WW;
    const float* zb = g_z + (size_t)bb * SIZE;

    float acc[4][4][4];
#pragma unroll
    for (int mi = 0; mi < 4; mi++)
#pragma unroll
        for (int ni = 0; ni < 4; ni++)
#pragma unroll
            for (int j = 0; j < 4; j++) acc[mi][ni][j] = 0.f;

    for (int t = 0; t < 9; ++t) {
        const int dy = t / 3 - 1, dx = t % 3 - 1;
        const int iy = yy + dy, ix = xx + dx;
        const bool valid = ((unsigned)iy < (unsigned)HH) &
                           ((unsigned)ix < (unsigned)WW);
        const float* abase = zb + iy * WW + ix;

        for (int c = 0; c < 4; ++c) {
            const int ic0 = c * 32;
            // ---- gather A chunk: [32 k][128 px] ----
#pragma unroll
            for (int i = 0; i < 16; i++) {
                int kk = krow + 2 * i;
                float v = valid ? __ldg(abase + (size_t)(ic0 + kk) * HW) : 0.f;
                As[kk * SK + px] = __uint_as_float(f2tf32(v));
            }
            // ---- load B chunk: [32 k][128 oc] (coalesced) ----
            const float* wbp = g_wt + ((size_t)t * CC + ic0 + krow) * CC + px;
#pragma unroll
            for (int i = 0; i < 16; i++)
                Bs[(krow + 2 * i) * SK + px] = wbp[(size_t)i * 2 * CC];
            __syncthreads();

            // ---- compute: 4 k-steps of m16n8k8 ----
#pragma unroll
            for (int ks = 0; ks < 4; ks++) {
                const int k0 = ks * 8;
                const float* A0 = As + (k0 + tig) * SK;
                const float* A4 = As + (k0 + tig + 4) * SK;
                const float* B0 = Bs + (k0 + tig) * SK;
                const float* B4 = Bs + (k0 + tig + 4) * SK;
                uint32_t afr[4][4], bfr[4][2];
#pragma unroll
                for (int mi = 0; mi < 4; mi++) {
                    int m = warp_m * 64 + mi * 16 + g;
                    afr[mi][0] = __float_as_uint(A0[m]);
                    afr[mi][1] = __float_as_uint(A0[m + 8]);
                    afr[mi][2] = __float_as_uint(A4[m]);
                    afr[mi][3] = __float_as_uint(A4[m + 8]);
                }
#pragma unroll
                for (int ni = 0; ni < 4; ni++) {
                    int n = warp_n * 32 + ni * 8 + g;
                    bfr[ni][0] = __float_as_uint(B0[n]);
                    bfr[ni][1] = __float_as_uint(B4[n]);
                }
#pragma unroll
                for (int mi = 0; mi < 4; mi++)
#pragma unroll
                    for (int ni = 0; ni < 4; ni++)
                        mma_tf32(acc[mi][ni], afr[mi], bfr[ni]);
            }
            __syncthreads();
        }
    }

    // ---- epilogue: bias+BN2d+LeakyReLU, scatter to NCHW ----
#pragma unroll
    for (int mi = 0; mi < 4; mi++) {
#pragma unroll
        for (int half = 0; half < 2; half++) {
            int row = warp_m * 64 + mi * 16 + g + half * 8;
            int gpo = blockIdx.x * 128 + row;
            int bo  = gpo / HW;
            int po  = gpo % HW;
            float* obase = out + (size_t)bo * SIZE + po;
#pragma unroll
            for (int ni = 0; ni < 4; ni++) {
#pragma unroll
                for (int jj = 0; jj < 2; jj++) {
                    int oc = warp_n * 32 + ni * 8 + 2 * tig + jj;
                    float v = fmaf(acc[mi][ni][half * 2 + jj],
                                   __ldg(&g_s2[oc]), __ldg(&g_sh2[oc]));
                    obase[(size_t)oc * HW] = (v > 0.f) ? v : SLOPE * v;
                }
            }
        }
    }
}

// ---------------------------------------------------------------------------
// launch
// ---------------------------------------------------------------------------
extern "C" void kernel_launch(void* const* d_in, const int* in_sizes, int n_in,
                              void* d_out, int out_size) {
    const float* ax   = (const float*)d_in[0];
    const float* mx   = (const float*)d_in[1];
    const float* cfc  = (const float*)d_in[2];
    const float* bng  = (const float*)d_in[3];
    const float* bnb  = (const float*)d_in[4];
    const float* bnm  = (const float*)d_in[5];
    const float* bnv  = (const float*)d_in[6];
    const float* cw   = (const float*)d_in[7];
    const float* cb   = (const float*)d_in[8];
    const float* g2   = (const float*)d_in[9];
    const float* b2   = (const float*)d_in[10];
    const float* m2   = (const float*)d_in[11];
    const float* v2   = (const float*)d_in[12];
    float* out = (float*)d_out;

    scrm_fuse1<<<(SIZE + 255) / 256, 256>>>(ax, mx, cfc, bng, bnb, bnm, bnv);
    scrm_wtrans<<<(9 * CC * CC + 255) / 256, 256>>>(cw);
    scrm_epiparams<<<1, CC>>>(cb, g2, b2, m2, v2);

    scrm_conv_mma<<<(BB * HW) / 128, 256>>>(out);   // 784 CTAs
}

// round 4
// speedup vs baseline: 3.1702x; 1.0110x over previous
#include <cuda_runtime.h>
#include <cstdint>

#define BB 32
#define CC 128
#define HH 56
#define WW 56
#define SIZE (CC*HH*WW)          // 401408
#define HW   (HH*WW)             // 3136
#define EPSV 1e-5f
#define SLOPE 0.1f
#define SK 136                    // smem row stride (floats), ≡ 8 mod 32
#define SST (64*SK)               // per-stage floats: A(32*SK) + B(32*SK)

// scratch (allocation-free rule: __device__ globals)
__device__ float g_z[BB*SIZE];        // 51.4 MB: z = leakyrelu(bn1(combine))
__device__ float g_wt[9*CC*CC];       // [tap][ic][oc], tf32-rounded weights
__device__ float g_s2[CC];            // fused epilogue scale
__device__ float g_sh2[CC];           // fused epilogue shift (incl. conv bias)

__device__ __forceinline__ uint32_t f2tf32(float v) {
    uint32_t r; asm("cvt.rna.tf32.f32 %0, %1;" : "=r"(r) : "f"(v)); return r;
}
__device__ __forceinline__ uint32_t smem_u32(const void* p) {
    uint32_t a;
    asm("{ .reg .u64 t; cvta.to.shared.u64 t, %1; cvt.u32.u64 %0, t; }"
        : "=r"(a) : "l"(p));
    return a;
}
__device__ __forceinline__ void mma_tf32(float* d, const uint32_t* a,
                                         const uint32_t* b) {
    asm volatile(
        "mma.sync.aligned.m16n8k8.row.col.f32.tf32.tf32.f32 "
        "{%0,%1,%2,%3}, {%4,%5,%6,%7}, {%8,%9}, {%0,%1,%2,%3};"
        : "+f"(d[0]), "+f"(d[1]), "+f"(d[2]), "+f"(d[3])
        : "r"(a[0]), "r"(a[1]), "r"(a[2]), "r"(a[3]),
          "r"(b[0]), "r"(b[1]));
}

// ---------------------------------------------------------------------------
// Kernel 1: elementwise combine + BN1d + LeakyReLU
// ---------------------------------------------------------------------------
__global__ void scrm_fuse1(const float* __restrict__ ax,
                           const float* __restrict__ mx,
                           const float* __restrict__ cfc,
                           const float* __restrict__ gamma,
                           const float* __restrict__ beta,
                           const float* __restrict__ mean,
                           const float* __restrict__ var) {
    int i = blockIdx.x * blockDim.x + threadIdx.x;
    if (i >= SIZE) return;
    float w0 = cfc[2 * i];
    float w1 = cfc[2 * i + 1];
    float s  = gamma[i] * rsqrtf(var[i] + EPSV);
    float sh = beta[i] - mean[i] * s;
    float ws0 = w0 * s;
    float ws1 = w1 * s;
#pragma unroll 4
    for (int b = 0; b < BB; b++) {
        int idx = b * SIZE + i;
        float z = fmaf(ws0, ax[idx], fmaf(ws1, mx[idx], sh));
        g_z[idx] = (z > 0.f) ? z : SLOPE * z;
    }
}

// ---------------------------------------------------------------------------
// Kernel 1b: weight transpose [oc][ic][3][3] -> [tap][ic][oc], tf32-rounded
// ---------------------------------------------------------------------------
__global__ void scrm_wtrans(const float* __restrict__ gw) {
    int i = blockIdx.x * 256 + threadIdx.x;      // over 9*128*128
    if (i >= 9 * CC * CC) return;
    int oc = i & 127;
    int ic = (i >> 7) & 127;
    int t  = i >> 14;
    float v = gw[oc * 1152 + ic * 9 + t];
    g_wt[i] = __uint_as_float(f2tf32(v));        // [t][ic][oc]
}

// ---------------------------------------------------------------------------
// Kernel 1c: fold conv bias + BN2d into per-oc scale/shift
// ---------------------------------------------------------------------------
__global__ void scrm_epiparams(const float* __restrict__ cb,
                               const float* __restrict__ g2,
                               const float* __restrict__ b2,
                               const float* __restrict__ m2,
                               const float* __restrict__ v2) {
    int oc = threadIdx.x;
    float s = g2[oc] * rsqrtf(v2[oc] + EPSV);
    g_s2[oc]  = s;
    g_sh2[oc] = fmaf(cb[oc] - m2[oc], s, b2[oc]);
}

// ---------------------------------------------------------------------------
// Kernel 2: tf32 mma.sync implicit-GEMM conv, cp.async double-buffered.
// CTA: 256 thr (8 warps, 2 M x 4 N). Block tile 128 px x 128 oc, K-chunk 32.
// 36 stages (9 taps x 4 ic-chunks); stage s+1 prefetched via cp.async while
// stage s computes. Smem k-major, stride 136 (conflict-free STS + LDS).
// ---------------------------------------------------------------------------
__global__ void __launch_bounds__(256, 2)
scrm_conv_mma(float* __restrict__ out) {
    extern __shared__ float sm[];   // 2 stages x (As[32*SK] + Bs[32*SK])

    const int tid  = threadIdx.x;
    const int wid  = tid >> 5;
    const int lane = tid & 31;
    const int warp_m = wid >> 2;    // 0..1
    const int warp_n = wid & 3;     // 0..3
    const int g   = lane >> 2;      // groupID 0..7
    const int tig = lane & 3;       // 0..3

    const int px   = tid & 127;     // gather: this thread's pixel column
    const int krow = tid >> 7;      // 0 or 1 (k rows krow, krow+2, ...)
    const int gp   = blockIdx.x * 128 + px;
    const int bb   = gp / HW;
    const int pp   = gp % HW;
    const int yy   = pp / WW, xx = pp % WW;
    const float* zb = g_z + (size_t)bb * SIZE;

    float acc[4][4][4];
#pragma unroll
    for (int mi = 0; mi < 4; mi++)
#pragma unroll
        for (int ni = 0; ni < 4; ni++)
#pragma unroll
            for (int j = 0; j < 4; j++) acc[mi][ni][j] = 0.f;

    // ---- stage prefetch: cp.async A-gather + B vector copy, one commit ----
    auto prefetch = [&](int s) {
        float* As = sm + (s & 1) * SST;
        float* Bs = As + 32 * SK;
        const int t = s >> 2, c = s & 3;
        const int t3 = t / 3;
        const int dy = t3 - 1, dx = (t - 3 * t3) - 1;
        const int iy = yy + dy, ix = xx + dx;
        const bool valid = ((unsigned)iy < (unsigned)HH) &
                           ((unsigned)ix < (unsigned)WW);
        const uint32_t asz = valid ? 4u : 0u;
        const float* ap = valid
            ? (zb + (size_t)(c * 32 + krow) * HW + iy * WW + ix)
            : zb;                                    // clamped, never read
        uint32_t adst = smem_u32(As + krow * SK + px);
#pragma unroll
        for (int i = 0; i < 16; i++) {
            asm volatile("cp.async.ca.shared.global [%0], [%1], 4, %2;"
                :: "r"(adst + (uint32_t)(i * 2 * SK * 4)),
                   "l"(ap + (size_t)i * 2 * HW), "r"(asz));
        }
        const float* wb = g_wt + ((size_t)t * CC + c * 32) * CC;
#pragma unroll
        for (int q = 0; q < 4; q++) {
            int idx = tid + 256 * q;        // 0..1023 = 32 rows x 32 float4
            int r = idx >> 5, j = idx & 31;
            asm volatile("cp.async.ca.shared.global [%0], [%1], 16;"
                :: "r"(smem_u32(Bs + r * SK + j * 4)),
                   "l"(wb + r * CC + j * 4));
        }
        asm volatile("cp.async.commit_group;" ::: "memory");
    };

    prefetch(0);
    for (int s = 0; s < 36; ++s) {
        if (s + 1 < 36) {
            prefetch(s + 1);
            asm volatile("cp.async.wait_group 1;" ::: "memory");
        } else {
            asm volatile("cp.async.wait_group 0;" ::: "memory");
        }
        __syncthreads();

        const float* As = sm + (s & 1) * SST;
        const float* Bs = As + 32 * SK;
#pragma unroll
        for (int ks = 0; ks < 4; ks++) {
            const int k0 = ks * 8;
            const float* A0 = As + (k0 + tig) * SK;
            const float* A4 = As + (k0 + tig + 4) * SK;
            const float* B0 = Bs + (k0 + tig) * SK;
            const float* B4 = Bs + (k0 + tig + 4) * SK;
            uint32_t afr[4][4], bfr[4][2];
#pragma unroll
            for (int mi = 0; mi < 4; mi++) {
                int m = warp_m * 64 + mi * 16 + g;
                afr[mi][0] = __float_as_uint(A0[m]);
                afr[mi][1] = __float_as_uint(A0[m + 8]);
                afr[mi][2] = __float_as_uint(A4[m]);
                afr[mi][3] = __float_as_uint(A4[m + 8]);
            }
#pragma unroll
            for (int ni = 0; ni < 4; ni++) {
                int n = warp_n * 32 + ni * 8 + g;
                bfr[ni][0] = __float_as_uint(B0[n]);
                bfr[ni][1] = __float_as_uint(B4[n]);
            }
#pragma unroll
            for (int mi = 0; mi < 4; mi++)
#pragma unroll
                for (int ni = 0; ni < 4; ni++)
                    mma_tf32(acc[mi][ni], afr[mi], bfr[ni]);
        }
        __syncthreads();
    }

    // ---- epilogue: bias+BN2d+LeakyReLU, scatter to NCHW ----
#pragma unroll
    for (int mi = 0; mi < 4; mi++) {
#pragma unroll
        for (int half = 0; half < 2; half++) {
            int row = warp_m * 64 + mi * 16 + g + half * 8;
            int gpo = blockIdx.x * 128 + row;
            int bo  = gpo / HW;
            int po  = gpo % HW;
            float* obase = out + (size_t)bo * SIZE + po;
#pragma unroll
            for (int ni = 0; ni < 4; ni++) {
#pragma unroll
                for (int jj = 0; jj < 2; jj++) {
                    int oc = warp_n * 32 + ni * 8 + 2 * tig + jj;
                    float v = fmaf(acc[mi][ni][half * 2 + jj],
                                   __ldg(&g_s2[oc]), __ldg(&g_sh2[oc]));
                    obase[(size_t)oc * HW] = (v > 0.f) ? v : SLOPE * v;
                }
            }
        }
    }
}

// ---------------------------------------------------------------------------
// launch
// ---------------------------------------------------------------------------
extern "C" void kernel_launch(void* const* d_in, const int* in_sizes, int n_in,
                              void* d_out, int out_size) {
    const float* ax   = (const float*)d_in[0];
    const float* mx   = (const float*)d_in[1];
    const float* cfc  = (const float*)d_in[2];
    const float* bng  = (const float*)d_in[3];
    const float* bnb  = (const float*)d_in[4];
    const float* bnm  = (const float*)d_in[5];
    const float* bnv  = (const float*)d_in[6];
    const float* cw   = (const float*)d_in[7];
    const float* cb   = (const float*)d_in[8];
    const float* g2   = (const float*)d_in[9];
    const float* b2   = (const float*)d_in[10];
    const float* m2   = (const float*)d_in[11];
    const float* v2   = (const float*)d_in[12];
    float* out = (float*)d_out;

    static bool attr_set = false;
    if (!attr_set) {
        cudaFuncSetAttribute(scrm_conv_mma,
                             cudaFuncAttributeMaxDynamicSharedMemorySize,
                             2 * SST * sizeof(float));
        attr_set = true;
    }

    scrm_fuse1<<<(SIZE + 255) / 256, 256>>>(ax, mx, cfc, bng, bnb, bnm, bnv);
    scrm_wtrans<<<(9 * CC * CC + 255) / 256, 256>>>(cw);
    scrm_epiparams<<<1, CC>>>(cb, g2, b2, m2, v2);

    scrm_conv_mma<<<(BB * HW) / 128, 256, 2 * SST * sizeof(float)>>>(out);
}